// round 13
// baseline (speedup 1.0000x reference)
#include <cuda_runtime.h>
#include <cuda_fp16.h>
#include <math.h>
#include <cstdint>

#define SQ   4096
#define EM   2048
#define NH   16
#define HD   128
#define QKVC (3*EM)

// ---------------------------------------------------------------------
// Scratch (allocation-free rule: device globals)
// ---------------------------------------------------------------------
__device__ __half g_qkvh[(size_t)SQ * QKVC];   // qkv (fp16)
__device__ __half g_ah[(size_t)SQ * EM];       // A (hs, then ctx) fp16
__device__ __half g_bh[(size_t)QKVC * EM];     // Wqkv fp16
__device__ __half g_bh2[(size_t)EM * EM];      // Wo fp16 (converted by gemm1 epilogue)

// ---------------------------------------------------------------------
// Portable PTX helpers
// ---------------------------------------------------------------------
__device__ __forceinline__ uint32_t smem_u32(const void* p) {
    uint32_t a;
    asm("{ .reg .u64 t; cvta.to.shared.u64 t, %1; cvt.u32.u64 %0, t; }" : "=r"(a) : "l"(p));
    return a;
}
__device__ __forceinline__ void cp_async16(uint32_t saddr, const void* gaddr) {
    asm volatile("cp.async.cg.shared.global [%0], [%1], 16;" :: "r"(saddr), "l"(gaddr));
}
__device__ __forceinline__ void cp_commit() { asm volatile("cp.async.commit_group;"); }
template <int N>
__device__ __forceinline__ void cp_wait() { asm volatile("cp.async.wait_group %0;" :: "n"(N)); }

__device__ __forceinline__ void ldsm4(uint32_t* r, uint32_t addr) {
    asm volatile("ldmatrix.sync.aligned.m8n8.x4.shared.b16 {%0,%1,%2,%3}, [%4];"
        : "=r"(r[0]), "=r"(r[1]), "=r"(r[2]), "=r"(r[3]) : "r"(addr));
}
__device__ __forceinline__ void ldsm4t(uint32_t* r, uint32_t addr) {
    asm volatile("ldmatrix.sync.aligned.m8n8.x4.trans.shared.b16 {%0,%1,%2,%3}, [%4];"
        : "=r"(r[0]), "=r"(r[1]), "=r"(r[2]), "=r"(r[3]) : "r"(addr));
}
__device__ __forceinline__ void mma16816(float* c, const uint32_t* a, uint32_t b0, uint32_t b1) {
    asm volatile("mma.sync.aligned.m16n8k16.row.col.f32.f16.f16.f32 "
        "{%0,%1,%2,%3}, {%4,%5,%6,%7}, {%8,%9}, {%0,%1,%2,%3};"
        : "+f"(c[0]), "+f"(c[1]), "+f"(c[2]), "+f"(c[3])
        : "r"(a[0]), "r"(a[1]), "r"(a[2]), "r"(a[3]), "r"(b0), "r"(b1));
}
__device__ __forceinline__ uint32_t pack_h2(float a, float b) {
    __half2 v = __floats2half2_rn(a, b);
    return *reinterpret_cast<uint32_t*>(&v);
}

// ---------------------------------------------------------------------
// Convert fp32 -> fp16 — 16 elems/thread; handles TWO arrays per launch
// ---------------------------------------------------------------------
__global__ __launch_bounds__(256)
void conv_f16_2(const float* __restrict__ x0, __half* __restrict__ h0, int n0,
                const float* __restrict__ x1, __half* __restrict__ h1, int n1)
{
    int base = (blockIdx.x * 256 + threadIdx.x) * 16;
    const float* x; __half* hp;
    if (base < n0) { x = x0 + base; hp = h0 + base; }
    else {
        base -= n0;
        if (base >= n1) return;
        x = x1 + base; hp = h1 + base;
    }
    float4 v0 = *(const float4*)(x);
    float4 v1 = *(const float4*)(x + 4);
    float4 v2 = *(const float4*)(x + 8);
    float4 v3 = *(const float4*)(x + 12);
    __half2 h[8];
    h[0] = __floats2half2_rn(v0.x, v0.y); h[1] = __floats2half2_rn(v0.z, v0.w);
    h[2] = __floats2half2_rn(v1.x, v1.y); h[3] = __floats2half2_rn(v1.z, v1.w);
    h[4] = __floats2half2_rn(v2.x, v2.y); h[5] = __floats2half2_rn(v2.z, v2.w);
    h[6] = __floats2half2_rn(v3.x, v3.y); h[7] = __floats2half2_rn(v3.z, v3.w);
    *(uint4*)(hp)     = *(uint4*)&h[0];
    *(uint4*)(hp + 8) = *(uint4*)&h[4];
}

// ---------------------------------------------------------------------
// Tensor-core GEMM: C = A[M,K] @ B[N,K]^T + bias[N]
// 64x128 CTA tile, 8 warps (2x4) of 32x32, 3-stage cp.async, 2 CTAs/SM.
// mode 0: C fp32; mode 1: Ch fp16.
// Optional fused side conversion: wsrc fp32 -> wdst fp16 (wn elems).
// ---------------------------------------------------------------------
#define STAGES 3
#define ATILE 5120            // 64 rows x 80B
#define SSTAGE 15360          // A 5120 + B 10240
#define GEMM_SMEM (STAGES * SSTAGE)   // 46080

__global__ __launch_bounds__(256, 2)
void gemm_mma(const __half* __restrict__ A, const __half* __restrict__ B,
              const float* __restrict__ bias, float* __restrict__ C,
              __half* __restrict__ Ch, int mode, int N, int K,
              const float* __restrict__ wsrc, __half* __restrict__ wdst, int wn)
{
    extern __shared__ __align__(128) char smem[];
    const uint32_t sbase = smem_u32(smem);

    const int tid  = threadIdx.x;
    const int lane = tid & 31;
    const int wid  = tid >> 5;

    // banded CTA swizzle (L2-friendly): 8 bm rows per band
    const int id    = blockIdx.y * gridDim.x + blockIdx.x;
    const int bandw = 8 * gridDim.x;
    const int band  = id / bandw;
    const int rem   = id - band * bandw;
    const int bm = (band * 8 + (rem & 7)) * 64;
    const int bn = (rem >> 3) * 128;

    const int wm = (wid >> 2) * 32;
    const int wn2 = (wid & 3) * 32;

    const uint32_t aoff = (uint32_t)((wm + (lane & 15)) * 80 + (lane >> 4) * 16);
    const uint32_t boff = (uint32_t)(ATILE + (wn2 + (lane & 15)) * 80 + (lane >> 4) * 16);

    const __half* Abase = A + (size_t)bm * K;
    const __half* Bbase = B + (size_t)bn * K;

    float c[2][4][4];
    #pragma unroll
    for (int i = 0; i < 2; i++)
        #pragma unroll
        for (int j = 0; j < 4; j++)
            #pragma unroll
            for (int q = 0; q < 4; q++) c[i][j][q] = 0.0f;

    const int nk = K >> 5;

    auto issue = [&](int kt, int slot) {
        const int koff = kt * 32;
        const uint32_t st = sbase + slot * SSTAGE;
        {
            int row = tid >> 2, c16 = tid & 3;
            cp_async16(st + row * 80 + c16 * 16,
                       Abase + (size_t)row * K + koff + c16 * 8);
        }
        #pragma unroll
        for (int it = 0; it < 2; it++) {
            int idx = tid + it * 256;
            int row = idx >> 2, c16 = idx & 3;
            cp_async16(st + ATILE + row * 80 + c16 * 16,
                       Bbase + (size_t)row * K + koff + c16 * 8);
        }
    };

    issue(0, 0); cp_commit();
    issue(1, 1); cp_commit();

    for (int kt = 0; kt < nk; kt++) {
        cp_wait<1>();
        __syncthreads();

        const int nxt = kt + 2;
        if (nxt < nk) { issue(nxt, nxt % STAGES); }
        cp_commit();

        const uint32_t st = sbase + (kt % STAGES) * SSTAGE;
        #pragma unroll
        for (int kk = 0; kk < 2; kk++) {
            uint32_t ah[2][4], bh[2][4];
            #pragma unroll
            for (int i = 0; i < 2; i++)
                ldsm4(ah[i], st + aoff + i * 1280 + kk * 32);
            #pragma unroll
            for (int j2 = 0; j2 < 2; j2++)
                ldsm4(bh[j2], st + boff + j2 * 1280 + kk * 32);
            #pragma unroll
            for (int i = 0; i < 2; i++)
                #pragma unroll
                for (int j = 0; j < 4; j++) {
                    const int j2 = j >> 1, sl = j & 1;
                    mma16816(c[i][j], ah[i], bh[j2][sl], bh[j2][sl + 2]);
                }
        }
    }

    const int g = lane >> 2, t = lane & 3;
    #pragma unroll
    for (int j = 0; j < 4; j++) {
        const int col = bn + wn2 + j * 8 + t * 2;
        const float b0 = bias[col], b1 = bias[col + 1];
        #pragma unroll
        for (int i = 0; i < 2; i++) {
            const int row0 = bm + wm + i * 16 + g;
            float x0 = c[i][j][0] + b0, x1 = c[i][j][1] + b1;
            float x2 = c[i][j][2] + b0, x3 = c[i][j][3] + b1;
            if (mode == 0) {
                *(float2*)(C + (size_t)row0 * N + col)       = make_float2(x0, x1);
                *(float2*)(C + (size_t)(row0 + 8) * N + col) = make_float2(x2, x3);
            } else {
                *(__half2*)(Ch + (size_t)row0 * N + col)       = __floats2half2_rn(x0, x1);
                *(__half2*)(Ch + (size_t)(row0 + 8) * N + col) = __floats2half2_rn(x2, x3);
            }
        }
    }

    // fused side conversion (wo fp32 -> fp16), spread across CTAs; ~free
    if (wsrc) {
        int base = (id * 256 + tid) * 16;
        if (base < wn) {
            float4 v0 = *(const float4*)(wsrc + base);
            float4 v1 = *(const float4*)(wsrc + base + 4);
            float4 v2 = *(const float4*)(wsrc + base + 8);
            float4 v3 = *(const float4*)(wsrc + base + 12);
            __half2 h[8];
            h[0] = __floats2half2_rn(v0.x, v0.y); h[1] = __floats2half2_rn(v0.z, v0.w);
            h[2] = __floats2half2_rn(v1.x, v1.y); h[3] = __floats2half2_rn(v1.z, v1.w);
            h[4] = __floats2half2_rn(v2.x, v2.y); h[5] = __floats2half2_rn(v2.z, v2.w);
            h[6] = __floats2half2_rn(v3.x, v3.y); h[7] = __floats2half2_rn(v3.z, v3.w);
            *(uint4*)(wdst + base)     = *(uint4*)&h[0];
            *(uint4*)(wdst + base + 8) = *(uint4*)&h[4];
        }
    }
}

// =====================================================================
// Tensorized flash attention (causal): Br=128, Bc=64, 8 warps
// Heavy/light interleaved grid: even blockIdx = heavy half (qb 31..16),
// odd = light half (qb 0..15) — pairs heavy CTAs with light co-residents.
// =====================================================================
#define ASTR 272
#define QTILE (128 * ASTR)
#define KVTILE (64 * ASTR)
#define KVSTAGE (2 * KVTILE)
#define FLASH_SMEM (QTILE + 2 * KVSTAGE)   // 104448 -> 2 CTAs/SM
#define QBTOT (SQ / 128)                    // 32

__global__ __launch_bounds__(256, 2)
void flash_attn_mma(const __half* __restrict__ qkvh, __half* __restrict__ ctxh)
{
    extern __shared__ __align__(128) char smem[];
    const uint32_t sb = smem_u32(smem);

    const int tid  = threadIdx.x;
    const int lane = tid & 31;
    const int wid  = tid >> 5;

    // heavy/light interleave
    const int b   = blockIdx.x;
    const int idx = b >> 1;
    const int h   = idx & (NH - 1);
    const int qb  = (b & 1) ? (idx >> 4) : (QBTOT - 1 - (idx >> 4));

    const int q0w = qb * 128 + wid * 16;
    const int nkb = 2 * qb + 2;
    const float qs = 0.08838834764831845f * 1.4426950408889634f;  // scale*log2(e)

    {
        const size_t qrow = (size_t)(qb * 128) * QKVC + h * HD;
        const __half* qsrc = qkvh + qrow;
        #pragma unroll
        for (int it = 0; it < 8; it++) {
            int i2 = tid + it * 256;
            int row = i2 >> 4, ch = i2 & 15;
            cp_async16(sb + row * ASTR + ch * 16,
                       qsrc + (size_t)row * QKVC + ch * 8);
        }
    }

    auto issueKV = [&](int kb, int slot) {
        const size_t roff = (size_t)(kb * 64) * QKVC + h * HD;
        const __half* base[2] = { qkvh + EM + roff, qkvh + 2 * EM + roff };
        const uint32_t st = sb + QTILE + slot * KVSTAGE;
        #pragma unroll
        for (int it = 0; it < 8; it++) {
            int i2 = tid + it * 256;
            int arr = i2 >> 10, rem = i2 & 1023;
            int row = rem >> 4, ch = rem & 15;
            cp_async16(st + arr * KVTILE + row * ASTR + ch * 16,
                       base[arr] + (size_t)row * QKVC + ch * 8);
        }
    };

    issueKV(0, 0); cp_commit();
    issueKV(1, 1); cp_commit();

    float m[2] = { -1e30f, -1e30f };
    float l[2] = { 0.0f, 0.0f };
    float o[16][4];
    #pragma unroll
    for (int n = 0; n < 16; n++)
        #pragma unroll
        for (int q = 0; q < 4; q++) o[n][q] = 0.0f;

    const int g = lane >> 2, t = lane & 3;
    const uint32_t qaddr = sb + (wid * 16 + (lane & 15)) * ASTR + (lane >> 4) * 16;
    const uint32_t kvlane = (uint32_t)((lane & 15) * ASTR + (lane >> 4) * 16);

    for (int kb = 0; kb < nkb; kb++) {
        cp_wait<1>();
        __syncthreads();

        const int slot = kb & 1;
        const uint32_t kB = sb + QTILE + slot * KVSTAGE;
        const uint32_t vB = kB + KVTILE;
        const bool skip = (kb * 64 > q0w + 15);

        if (!skip) {
            float s[8][4];
            #pragma unroll
            for (int j = 0; j < 8; j++)
                #pragma unroll
                for (int q = 0; q < 4; q++) s[j][q] = 0.0f;

            #pragma unroll
            for (int ks = 0; ks < 8; ks++) {
                uint32_t ah4[4];
                ldsm4(ah4, qaddr + ks * 32);
                #pragma unroll
                for (int p2 = 0; p2 < 4; p2++) {
                    uint32_t bh4[4];
                    ldsm4(bh4, kB + kvlane + p2 * (16 * ASTR) + ks * 32);
                    #pragma unroll
                    for (int sl = 0; sl < 2; sl++)
                        mma16816(s[p2 * 2 + sl], ah4, bh4[sl], bh4[sl + 2]);
                }
            }

            const bool dm = (kb * 64 + 63 > q0w);
            const int r0 = q0w + g, r1 = q0w + 8 + g;
            float mx0 = -1e30f, mx1 = -1e30f;
            #pragma unroll
            for (int j = 0; j < 8; j++) {
                const int col = kb * 64 + 8 * j + 2 * t;
                float v0 = s[j][0] * qs, v1 = s[j][1] * qs;
                float v2 = s[j][2] * qs, v3 = s[j][3] * qs;
                if (dm) {
                    if (col     > r0) v0 = -1e30f;
                    if (col + 1 > r0) v1 = -1e30f;
                    if (col     > r1) v2 = -1e30f;
                    if (col + 1 > r1) v3 = -1e30f;
                }
                s[j][0] = v0; s[j][1] = v1; s[j][2] = v2; s[j][3] = v3;
                mx0 = fmaxf(mx0, fmaxf(v0, v1));
                mx1 = fmaxf(mx1, fmaxf(v2, v3));
            }
            mx0 = fmaxf(mx0, __shfl_xor_sync(0xffffffffu, mx0, 1));
            mx0 = fmaxf(mx0, __shfl_xor_sync(0xffffffffu, mx0, 2));
            mx1 = fmaxf(mx1, __shfl_xor_sync(0xffffffffu, mx1, 1));
            mx1 = fmaxf(mx1, __shfl_xor_sync(0xffffffffu, mx1, 2));

            const float mn0 = fmaxf(m[0], mx0);
            const float mn1 = fmaxf(m[1], mx1);
            float rs0 = 0.0f, rs1 = 0.0f;
            #pragma unroll
            for (int j = 0; j < 8; j++) {
                s[j][0] = exp2f(s[j][0] - mn0);
                s[j][1] = exp2f(s[j][1] - mn0);
                s[j][2] = exp2f(s[j][2] - mn1);
                s[j][3] = exp2f(s[j][3] - mn1);
                rs0 += s[j][0] + s[j][1];
                rs1 += s[j][2] + s[j][3];
            }
            rs0 += __shfl_xor_sync(0xffffffffu, rs0, 1);
            rs0 += __shfl_xor_sync(0xffffffffu, rs0, 2);
            rs1 += __shfl_xor_sync(0xffffffffu, rs1, 1);
            rs1 += __shfl_xor_sync(0xffffffffu, rs1, 2);

            const float f0 = exp2f(m[0] - mn0);
            const float f1 = exp2f(m[1] - mn1);
            l[0] = l[0] * f0 + rs0; l[1] = l[1] * f1 + rs1;
            m[0] = mn0; m[1] = mn1;
            #pragma unroll
            for (int n = 0; n < 16; n++) {
                o[n][0] *= f0; o[n][1] *= f0;
                o[n][2] *= f1; o[n][3] *= f1;
            }

            #pragma unroll
            for (int jp = 0; jp < 4; jp++) {
                uint32_t ph[4];
                {
                    const float* p0 = s[2 * jp];
                    const float* p1 = s[2 * jp + 1];
                    ph[0] = pack_h2(p0[0], p0[1]);
                    ph[1] = pack_h2(p0[2], p0[3]);
                    ph[2] = pack_h2(p1[0], p1[1]);
                    ph[3] = pack_h2(p1[2], p1[3]);
                }
                #pragma unroll
                for (int np = 0; np < 8; np++) {
                    uint32_t bh4[4];
                    ldsm4t(bh4, vB + kvlane + jp * (16 * ASTR) + np * 32);
                    mma16816(o[2 * np],     ph, bh4[0], bh4[1]);
                    mma16816(o[2 * np + 1], ph, bh4[2], bh4[3]);
                }
            }
        }

        __syncthreads();
        if (kb + 2 < nkb) issueKV(kb + 2, slot);
        cp_commit();
    }

    const float inv0 = 1.0f / l[0];
    const float inv1 = 1.0f / l[1];
    const int r0 = q0w + g, r1 = q0w + 8 + g;
    #pragma unroll
    for (int n = 0; n < 16; n++) {
        const int col = h * HD + n * 8 + 2 * t;
        *(__half2*)(ctxh + (size_t)r0 * EM + col) =
            __floats2half2_rn(o[n][0] * inv0, o[n][1] * inv0);
        *(__half2*)(ctxh + (size_t)r1 * EM + col) =
            __floats2half2_rn(o[n][2] * inv1, o[n][3] * inv1);
    }
}

// =====================================================================
extern "C" void kernel_launch(void* const* d_in, const int* in_sizes, int n_in,
                              void* d_out, int out_size)
{
    (void)in_sizes; (void)n_in; (void)out_size;
    const float* hs   = (const float*)d_in[0];
    const float* wqkv = (const float*)d_in[1];
    const float* bqkv = (const float*)d_in[2];
    const float* wo   = (const float*)d_in[3];
    const float* bo   = (const float*)d_in[4];
    float* out = (float*)d_out;

    __half *qkvh, *ah, *bh, *bh2;
    cudaGetSymbolAddress((void**)&qkvh, g_qkvh);
    cudaGetSymbolAddress((void**)&ah, g_ah);
    cudaGetSymbolAddress((void**)&bh, g_bh);
    cudaGetSymbolAddress((void**)&bh2, g_bh2);

    cudaFuncSetAttribute(gemm_mma, cudaFuncAttributeMaxDynamicSharedMemorySize, GEMM_SMEM);
    cudaFuncSetAttribute(flash_attn_mma, cudaFuncAttributeMaxDynamicSharedMemorySize, FLASH_SMEM);

    // 1) convert hs + Wqkv to fp16 in ONE launch
    const int n0 = SQ * EM, n1 = QKVC * EM;
    conv_f16_2<<<((n0 + n1) / 16 + 255) / 256, 256>>>(hs, ah, n0, wqkv, bh, n1);

    // 2) QKV projection -> fp16  (+ fused Wo fp32->fp16 conversion into bh2)
    dim3 g1(QKVC / 128, SQ / 64);
    gemm_mma<<<g1, 256, GEMM_SMEM>>>(ah, bh, bqkv, nullptr, qkvh, 1, QKVC, EM,
                                     wo, bh2, EM * EM);

    // 3) causal flash attention -> ctx fp16 (overwrites ah)
    flash_attn_mma<<<(SQ / 128) * NH, 256, FLASH_SMEM>>>(qkvh, ah);

    // 4) output projection -> fp32 out (weights from bh2)
    dim3 g3(EM / 128, SQ / 64);
    gemm_mma<<<g3, 256, GEMM_SMEM>>>(ah, bh2, bo, out, nullptr, 0, EM, EM,
                                     nullptr, nullptr, 0);
}

// round 14
// speedup vs baseline: 1.0603x; 1.0603x over previous
#include <cuda_runtime.h>
#include <cuda_fp16.h>
#include <math.h>
#include <cstdint>

#define SQ   4096
#define EM   2048
#define NH   16
#define HD   128
#define QKVC (3*EM)

// ---------------------------------------------------------------------
// Scratch (allocation-free rule: device globals)
// ---------------------------------------------------------------------
__device__ __half g_qkvh[(size_t)SQ * QKVC];   // qkv (fp16)
__device__ __half g_ah[(size_t)SQ * EM];       // A (hs, then ctx) fp16
__device__ __half g_bh[(size_t)QKVC * EM];     // Wqkv fp16
__device__ __half g_bh2[(size_t)EM * EM];      // Wo fp16 (converted by gemm1 epilogue)

// ---------------------------------------------------------------------
// Portable PTX helpers
// ---------------------------------------------------------------------
__device__ __forceinline__ uint32_t smem_u32(const void* p) {
    uint32_t a;
    asm("{ .reg .u64 t; cvta.to.shared.u64 t, %1; cvt.u32.u64 %0, t; }" : "=r"(a) : "l"(p));
    return a;
}
__device__ __forceinline__ void cp_async16(uint32_t saddr, const void* gaddr) {
    asm volatile("cp.async.cg.shared.global [%0], [%1], 16;" :: "r"(saddr), "l"(gaddr));
}
__device__ __forceinline__ void cp_commit() { asm volatile("cp.async.commit_group;"); }
template <int N>
__device__ __forceinline__ void cp_wait() { asm volatile("cp.async.wait_group %0;" :: "n"(N)); }

__device__ __forceinline__ void ldsm4(uint32_t* r, uint32_t addr) {
    asm volatile("ldmatrix.sync.aligned.m8n8.x4.shared.b16 {%0,%1,%2,%3}, [%4];"
        : "=r"(r[0]), "=r"(r[1]), "=r"(r[2]), "=r"(r[3]) : "r"(addr));
}
__device__ __forceinline__ void ldsm4t(uint32_t* r, uint32_t addr) {
    asm volatile("ldmatrix.sync.aligned.m8n8.x4.trans.shared.b16 {%0,%1,%2,%3}, [%4];"
        : "=r"(r[0]), "=r"(r[1]), "=r"(r[2]), "=r"(r[3]) : "r"(addr));
}
__device__ __forceinline__ void mma16816(float* c, const uint32_t* a, uint32_t b0, uint32_t b1) {
    asm volatile("mma.sync.aligned.m16n8k16.row.col.f32.f16.f16.f32 "
        "{%0,%1,%2,%3}, {%4,%5,%6,%7}, {%8,%9}, {%0,%1,%2,%3};"
        : "+f"(c[0]), "+f"(c[1]), "+f"(c[2]), "+f"(c[3])
        : "r"(a[0]), "r"(a[1]), "r"(a[2]), "r"(a[3]), "r"(b0), "r"(b1));
}
__device__ __forceinline__ uint32_t pack_h2(float a, float b) {
    __half2 v = __floats2half2_rn(a, b);
    return *reinterpret_cast<uint32_t*>(&v);
}

// ---------------------------------------------------------------------
// Convert fp32 -> fp16 — 16 elems/thread; handles TWO arrays per launch
// ---------------------------------------------------------------------
__global__ __launch_bounds__(256)
void conv_f16_2(const float* __restrict__ x0, __half* __restrict__ h0, int n0,
                const float* __restrict__ x1, __half* __restrict__ h1, int n1)
{
    int base = (blockIdx.x * 256 + threadIdx.x) * 16;
    const float* x; __half* hp;
    if (base < n0) { x = x0 + base; hp = h0 + base; }
    else {
        base -= n0;
        if (base >= n1) return;
        x = x1 + base; hp = h1 + base;
    }
    float4 v0 = *(const float4*)(x);
    float4 v1 = *(const float4*)(x + 4);
    float4 v2 = *(const float4*)(x + 8);
    float4 v3 = *(const float4*)(x + 12);
    __half2 h[8];
    h[0] = __floats2half2_rn(v0.x, v0.y); h[1] = __floats2half2_rn(v0.z, v0.w);
    h[2] = __floats2half2_rn(v1.x, v1.y); h[3] = __floats2half2_rn(v1.z, v1.w);
    h[4] = __floats2half2_rn(v2.x, v2.y); h[5] = __floats2half2_rn(v2.z, v2.w);
    h[6] = __floats2half2_rn(v3.x, v3.y); h[7] = __floats2half2_rn(v3.z, v3.w);
    *(uint4*)(hp)     = *(uint4*)&h[0];
    *(uint4*)(hp + 8) = *(uint4*)&h[4];
}

// ---------------------------------------------------------------------
// Tensor-core GEMM: C = A[M,K] @ B[N,K]^T + bias[N]
// 64x128 CTA tile, 8 warps (2x4) of 32x32, 3-stage cp.async, 2 CTAs/SM.
// mode 0: C fp32; mode 1: Ch fp16.
// Optional fused side conversion: wsrc fp32 -> wdst fp16 (wn elems).
// ---------------------------------------------------------------------
#define STAGES 3
#define ATILE 5120            // 64 rows x 80B
#define SSTAGE 15360          // A 5120 + B 10240
#define GEMM_SMEM (STAGES * SSTAGE)   // 46080

__global__ __launch_bounds__(256, 2)
void gemm_mma(const __half* __restrict__ A, const __half* __restrict__ B,
              const float* __restrict__ bias, float* __restrict__ C,
              __half* __restrict__ Ch, int mode, int N, int K,
              const float* __restrict__ wsrc, __half* __restrict__ wdst, int wn)
{
    extern __shared__ __align__(128) char smem[];
    const uint32_t sbase = smem_u32(smem);

    const int tid  = threadIdx.x;
    const int lane = tid & 31;
    const int wid  = tid >> 5;

    // banded CTA swizzle (L2-friendly): 8 bm rows per band
    const int id    = blockIdx.y * gridDim.x + blockIdx.x;
    const int bandw = 8 * gridDim.x;
    const int band  = id / bandw;
    const int rem   = id - band * bandw;
    const int bm = (band * 8 + (rem & 7)) * 64;
    const int bn = (rem >> 3) * 128;

    const int wm = (wid >> 2) * 32;
    const int wn2 = (wid & 3) * 32;

    const uint32_t aoff = (uint32_t)((wm + (lane & 15)) * 80 + (lane >> 4) * 16);
    const uint32_t boff = (uint32_t)(ATILE + (wn2 + (lane & 15)) * 80 + (lane >> 4) * 16);

    const __half* Abase = A + (size_t)bm * K;
    const __half* Bbase = B + (size_t)bn * K;

    float c[2][4][4];
    #pragma unroll
    for (int i = 0; i < 2; i++)
        #pragma unroll
        for (int j = 0; j < 4; j++)
            #pragma unroll
            for (int q = 0; q < 4; q++) c[i][j][q] = 0.0f;

    const int nk = K >> 5;

    auto issue = [&](int kt, int slot) {
        const int koff = kt * 32;
        const uint32_t st = sbase + slot * SSTAGE;
        {
            int row = tid >> 2, c16 = tid & 3;
            cp_async16(st + row * 80 + c16 * 16,
                       Abase + (size_t)row * K + koff + c16 * 8);
        }
        #pragma unroll
        for (int it = 0; it < 2; it++) {
            int idx = tid + it * 256;
            int row = idx >> 2, c16 = idx & 3;
            cp_async16(st + ATILE + row * 80 + c16 * 16,
                       Bbase + (size_t)row * K + koff + c16 * 8);
        }
    };

    issue(0, 0); cp_commit();
    issue(1, 1); cp_commit();

    for (int kt = 0; kt < nk; kt++) {
        cp_wait<1>();
        __syncthreads();

        const int nxt = kt + 2;
        if (nxt < nk) { issue(nxt, nxt % STAGES); }
        cp_commit();

        const uint32_t st = sbase + (kt % STAGES) * SSTAGE;
        #pragma unroll
        for (int kk = 0; kk < 2; kk++) {
            uint32_t ah[2][4], bh[2][4];
            #pragma unroll
            for (int i = 0; i < 2; i++)
                ldsm4(ah[i], st + aoff + i * 1280 + kk * 32);
            #pragma unroll
            for (int j2 = 0; j2 < 2; j2++)
                ldsm4(bh[j2], st + boff + j2 * 1280 + kk * 32);
            #pragma unroll
            for (int i = 0; i < 2; i++)
                #pragma unroll
                for (int j = 0; j < 4; j++) {
                    const int j2 = j >> 1, sl = j & 1;
                    mma16816(c[i][j], ah[i], bh[j2][sl], bh[j2][sl + 2]);
                }
        }
    }

    const int g = lane >> 2, t = lane & 3;
    #pragma unroll
    for (int j = 0; j < 4; j++) {
        const int col = bn + wn2 + j * 8 + t * 2;
        const float b0 = bias[col], b1 = bias[col + 1];
        #pragma unroll
        for (int i = 0; i < 2; i++) {
            const int row0 = bm + wm + i * 16 + g;
            float x0 = c[i][j][0] + b0, x1 = c[i][j][1] + b1;
            float x2 = c[i][j][2] + b0, x3 = c[i][j][3] + b1;
            if (mode == 0) {
                *(float2*)(C + (size_t)row0 * N + col)       = make_float2(x0, x1);
                *(float2*)(C + (size_t)(row0 + 8) * N + col) = make_float2(x2, x3);
            } else {
                *(__half2*)(Ch + (size_t)row0 * N + col)       = __floats2half2_rn(x0, x1);
                *(__half2*)(Ch + (size_t)(row0 + 8) * N + col) = __floats2half2_rn(x2, x3);
            }
        }
    }

    // fused side conversion (Wo fp32 -> fp16), spread across CTAs
    if (wsrc) {
        int base = (id * 256 + tid) * 16;
        if (base < wn) {
            float4 v0 = *(const float4*)(wsrc + base);
            float4 v1 = *(const float4*)(wsrc + base + 4);
            float4 v2 = *(const float4*)(wsrc + base + 8);
            float4 v3 = *(const float4*)(wsrc + base + 12);
            __half2 h[8];
            h[0] = __floats2half2_rn(v0.x, v0.y); h[1] = __floats2half2_rn(v0.z, v0.w);
            h[2] = __floats2half2_rn(v1.x, v1.y); h[3] = __floats2half2_rn(v1.z, v1.w);
            h[4] = __floats2half2_rn(v2.x, v2.y); h[5] = __floats2half2_rn(v2.z, v2.w);
            h[6] = __floats2half2_rn(v3.x, v3.y); h[7] = __floats2half2_rn(v3.z, v3.w);
            *(uint4*)(wdst + base)     = *(uint4*)&h[0];
            *(uint4*)(wdst + base + 8) = *(uint4*)&h[4];
        }
    }
}

// =====================================================================
// Tensorized flash attention (causal): Br=128, Bc=64, 8 warps
// 1-D grid, all-heaviest-first across heads (R12 proven order).
// =====================================================================
#define ASTR 272
#define QTILE (128 * ASTR)
#define KVTILE (64 * ASTR)
#define KVSTAGE (2 * KVTILE)
#define FLASH_SMEM (QTILE + 2 * KVSTAGE)   // 104448 -> 2 CTAs/SM

__global__ __launch_bounds__(256, 2)
void flash_attn_mma(const __half* __restrict__ qkvh, __half* __restrict__ ctxh)
{
    extern __shared__ __align__(128) char smem[];
    const uint32_t sb = smem_u32(smem);

    const int tid  = threadIdx.x;
    const int lane = tid & 31;
    const int wid  = tid >> 5;
    const int h  = blockIdx.x & (NH - 1);
    const int qb = (SQ / 128) - 1 - (blockIdx.x >> 4);
    const int q0w = qb * 128 + wid * 16;
    const int nkb = 2 * qb + 2;
    const float qs = 0.08838834764831845f * 1.4426950408889634f;  // scale*log2(e)

    {
        const size_t qrow = (size_t)(qb * 128) * QKVC + h * HD;
        const __half* qsrc = qkvh + qrow;
        #pragma unroll
        for (int it = 0; it < 8; it++) {
            int idx = tid + it * 256;
            int row = idx >> 4, ch = idx & 15;
            cp_async16(sb + row * ASTR + ch * 16,
                       qsrc + (size_t)row * QKVC + ch * 8);
        }
    }

    auto issueKV = [&](int kb, int slot) {
        const size_t roff = (size_t)(kb * 64) * QKVC + h * HD;
        const __half* base[2] = { qkvh + EM + roff, qkvh + 2 * EM + roff };
        const uint32_t st = sb + QTILE + slot * KVSTAGE;
        #pragma unroll
        for (int it = 0; it < 8; it++) {
            int idx = tid + it * 256;
            int arr = idx >> 10, rem = idx & 1023;
            int row = rem >> 4, ch = rem & 15;
            cp_async16(st + arr * KVTILE + row * ASTR + ch * 16,
                       base[arr] + (size_t)row * QKVC + ch * 8);
        }
    };

    issueKV(0, 0); cp_commit();
    issueKV(1, 1); cp_commit();

    float m[2] = { -1e30f, -1e30f };
    float l[2] = { 0.0f, 0.0f };
    float o[16][4];
    #pragma unroll
    for (int n = 0; n < 16; n++)
        #pragma unroll
        for (int q = 0; q < 4; q++) o[n][q] = 0.0f;

    const int g = lane >> 2, t = lane & 3;
    const uint32_t qaddr = sb + (wid * 16 + (lane & 15)) * ASTR + (lane >> 4) * 16;
    const uint32_t kvlane = (uint32_t)((lane & 15) * ASTR + (lane >> 4) * 16);

    for (int kb = 0; kb < nkb; kb++) {
        cp_wait<1>();
        __syncthreads();

        const int slot = kb & 1;
        const uint32_t kB = sb + QTILE + slot * KVSTAGE;
        const uint32_t vB = kB + KVTILE;
        const bool skip = (kb * 64 > q0w + 15);

        if (!skip) {
            float s[8][4];
            #pragma unroll
            for (int j = 0; j < 8; j++)
                #pragma unroll
                for (int q = 0; q < 4; q++) s[j][q] = 0.0f;

            #pragma unroll
            for (int ks = 0; ks < 8; ks++) {
                uint32_t ah4[4];
                ldsm4(ah4, qaddr + ks * 32);
                #pragma unroll
                for (int p2 = 0; p2 < 4; p2++) {
                    uint32_t bh4[4];
                    ldsm4(bh4, kB + kvlane + p2 * (16 * ASTR) + ks * 32);
                    #pragma unroll
                    for (int sl = 0; sl < 2; sl++)
                        mma16816(s[p2 * 2 + sl], ah4, bh4[sl], bh4[sl + 2]);
                }
            }

            const bool dm = (kb * 64 + 63 > q0w);
            const int r0 = q0w + g, r1 = q0w + 8 + g;
            float mx0 = -1e30f, mx1 = -1e30f;
            #pragma unroll
            for (int j = 0; j < 8; j++) {
                const int col = kb * 64 + 8 * j + 2 * t;
                float v0 = s[j][0] * qs, v1 = s[j][1] * qs;
                float v2 = s[j][2] * qs, v3 = s[j][3] * qs;
                if (dm) {
                    if (col     > r0) v0 = -1e30f;
                    if (col + 1 > r0) v1 = -1e30f;
                    if (col     > r1) v2 = -1e30f;
                    if (col + 1 > r1) v3 = -1e30f;
                }
                s[j][0] = v0; s[j][1] = v1; s[j][2] = v2; s[j][3] = v3;
                mx0 = fmaxf(mx0, fmaxf(v0, v1));
                mx1 = fmaxf(mx1, fmaxf(v2, v3));
            }
            mx0 = fmaxf(mx0, __shfl_xor_sync(0xffffffffu, mx0, 1));
            mx0 = fmaxf(mx0, __shfl_xor_sync(0xffffffffu, mx0, 2));
            mx1 = fmaxf(mx1, __shfl_xor_sync(0xffffffffu, mx1, 1));
            mx1 = fmaxf(mx1, __shfl_xor_sync(0xffffffffu, mx1, 2));

            const float mn0 = fmaxf(m[0], mx0);
            const float mn1 = fmaxf(m[1], mx1);
            float rs0 = 0.0f, rs1 = 0.0f;
            #pragma unroll
            for (int j = 0; j < 8; j++) {
                s[j][0] = exp2f(s[j][0] - mn0);
                s[j][1] = exp2f(s[j][1] - mn0);
                s[j][2] = exp2f(s[j][2] - mn1);
                s[j][3] = exp2f(s[j][3] - mn1);
                rs0 += s[j][0] + s[j][1];
                rs1 += s[j][2] + s[j][3];
            }
            rs0 += __shfl_xor_sync(0xffffffffu, rs0, 1);
            rs0 += __shfl_xor_sync(0xffffffffu, rs0, 2);
            rs1 += __shfl_xor_sync(0xffffffffu, rs1, 1);
            rs1 += __shfl_xor_sync(0xffffffffu, rs1, 2);

            const float f0 = exp2f(m[0] - mn0);
            const float f1 = exp2f(m[1] - mn1);
            l[0] = l[0] * f0 + rs0; l[1] = l[1] * f1 + rs1;
            m[0] = mn0; m[1] = mn1;
            #pragma unroll
            for (int n = 0; n < 16; n++) {
                o[n][0] *= f0; o[n][1] *= f0;
                o[n][2] *= f1; o[n][3] *= f1;
            }

            #pragma unroll
            for (int jp = 0; jp < 4; jp++) {
                uint32_t ph[4];
                {
                    const float* p0 = s[2 * jp];
                    const float* p1 = s[2 * jp + 1];
                    ph[0] = pack_h2(p0[0], p0[1]);
                    ph[1] = pack_h2(p0[2], p0[3]);
                    ph[2] = pack_h2(p1[0], p1[1]);
                    ph[3] = pack_h2(p1[2], p1[3]);
                }
                #pragma unroll
                for (int np = 0; np < 8; np++) {
                    uint32_t bh4[4];
                    ldsm4t(bh4, vB + kvlane + jp * (16 * ASTR) + np * 32);
                    mma16816(o[2 * np],     ph, bh4[0], bh4[1]);
                    mma16816(o[2 * np + 1], ph, bh4[2], bh4[3]);
                }
            }
        }

        __syncthreads();
        if (kb + 2 < nkb) issueKV(kb + 2, slot);
        cp_commit();
    }

    const float inv0 = 1.0f / l[0];
    const float inv1 = 1.0f / l[1];
    const int r0 = q0w + g, r1 = q0w + 8 + g;
    #pragma unroll
    for (int n = 0; n < 16; n++) {
        const int col = h * HD + n * 8 + 2 * t;
        *(__half2*)(ctxh + (size_t)r0 * EM + col) =
            __floats2half2_rn(o[n][0] * inv0, o[n][1] * inv0);
        *(__half2*)(ctxh + (size_t)r1 * EM + col) =
            __floats2half2_rn(o[n][2] * inv1, o[n][3] * inv1);
    }
}

// =====================================================================
extern "C" void kernel_launch(void* const* d_in, const int* in_sizes, int n_in,
                              void* d_out, int out_size)
{
    (void)in_sizes; (void)n_in; (void)out_size;
    const float* hs   = (const float*)d_in[0];
    const float* wqkv = (const float*)d_in[1];
    const float* bqkv = (const float*)d_in[2];
    const float* wo   = (const float*)d_in[3];
    const float* bo   = (const float*)d_in[4];
    float* out = (float*)d_out;

    __half *qkvh, *ah, *bh, *bh2;
    cudaGetSymbolAddress((void**)&qkvh, g_qkvh);
    cudaGetSymbolAddress((void**)&ah, g_ah);
    cudaGetSymbolAddress((void**)&bh, g_bh);
    cudaGetSymbolAddress((void**)&bh2, g_bh2);

    cudaFuncSetAttribute(gemm_mma, cudaFuncAttributeMaxDynamicSharedMemorySize, GEMM_SMEM);
    cudaFuncSetAttribute(flash_attn_mma, cudaFuncAttributeMaxDynamicSharedMemorySize, FLASH_SMEM);

    // 1) convert hs + Wqkv to fp16 in ONE launch
    const int n0 = SQ * EM, n1 = QKVC * EM;
    conv_f16_2<<<((n0 + n1) / 16 + 255) / 256, 256>>>(hs, ah, n0, wqkv, bh, n1);

    // 2) QKV projection -> fp16  (+ fused Wo fp32->fp16 conversion into bh2)
    dim3 g1(QKVC / 128, SQ / 64);
    gemm_mma<<<g1, 256, GEMM_SMEM>>>(ah, bh, bqkv, nullptr, qkvh, 1, QKVC, EM,
                                     wo, bh2, EM * EM);

    // 3) causal flash attention -> ctx fp16 (overwrites ah) — R12 ordering
    flash_attn_mma<<<(SQ / 128) * NH, 256, FLASH_SMEM>>>(qkvh, ah);

    // 4) output projection -> fp32 out (weights from bh2)
    dim3 g3(EM / 128, SQ / 64);
    gemm_mma<<<g3, 256, GEMM_SMEM>>>(ah, bh2, bo, out, nullptr, 0, EM, EM,
                                     nullptr, nullptr, 0);
}

// round 15
// speedup vs baseline: 1.1025x; 1.0398x over previous
#include <cuda_runtime.h>
#include <cuda_fp16.h>
#include <math.h>
#include <cstdint>

#define SQ   4096
#define EM   2048
#define NH   16
#define HD   128
#define QKVC (3*EM)

// ---------------------------------------------------------------------
// Scratch (allocation-free rule: device globals)
// ---------------------------------------------------------------------
__device__ __half g_qkvh[(size_t)SQ * QKVC];   // qkv (fp16)
__device__ __half g_ah[(size_t)SQ * EM];       // A (hs, then ctx) fp16
__device__ __half g_bh[(size_t)QKVC * EM];     // Wqkv fp16
__device__ __half g_bh2[(size_t)EM * EM];      // Wo fp16

// ---------------------------------------------------------------------
// Portable PTX helpers
// ---------------------------------------------------------------------
__device__ __forceinline__ uint32_t smem_u32(const void* p) {
    uint32_t a;
    asm("{ .reg .u64 t; cvta.to.shared.u64 t, %1; cvt.u32.u64 %0, t; }" : "=r"(a) : "l"(p));
    return a;
}
__device__ __forceinline__ void cp_async16(uint32_t saddr, const void* gaddr) {
    asm volatile("cp.async.cg.shared.global [%0], [%1], 16;" :: "r"(saddr), "l"(gaddr));
}
__device__ __forceinline__ void cp_commit() { asm volatile("cp.async.commit_group;"); }
template <int N>
__device__ __forceinline__ void cp_wait() { asm volatile("cp.async.wait_group %0;" :: "n"(N)); }

__device__ __forceinline__ void ldsm4(uint32_t* r, uint32_t addr) {
    asm volatile("ldmatrix.sync.aligned.m8n8.x4.shared.b16 {%0,%1,%2,%3}, [%4];"
        : "=r"(r[0]), "=r"(r[1]), "=r"(r[2]), "=r"(r[3]) : "r"(addr));
}
__device__ __forceinline__ void ldsm4t(uint32_t* r, uint32_t addr) {
    asm volatile("ldmatrix.sync.aligned.m8n8.x4.trans.shared.b16 {%0,%1,%2,%3}, [%4];"
        : "=r"(r[0]), "=r"(r[1]), "=r"(r[2]), "=r"(r[3]) : "r"(addr));
}
__device__ __forceinline__ void mma16816(float* c, const uint32_t* a, uint32_t b0, uint32_t b1) {
    asm volatile("mma.sync.aligned.m16n8k16.row.col.f32.f16.f16.f32 "
        "{%0,%1,%2,%3}, {%4,%5,%6,%7}, {%8,%9}, {%0,%1,%2,%3};"
        : "+f"(c[0]), "+f"(c[1]), "+f"(c[2]), "+f"(c[3])
        : "r"(a[0]), "r"(a[1]), "r"(a[2]), "r"(a[3]), "r"(b0), "r"(b1));
}
__device__ __forceinline__ uint32_t pack_h2(float a, float b) {
    __half2 v = __floats2half2_rn(a, b);
    return *reinterpret_cast<uint32_t*>(&v);
}

// ---------------------------------------------------------------------
// Convert fp32 -> fp16 — 16 elems/thread; THREE arrays per launch
// ---------------------------------------------------------------------
__global__ __launch_bounds__(256)
void conv_f16_3(const float* __restrict__ x0, __half* __restrict__ h0, int n0,
                const float* __restrict__ x1, __half* __restrict__ h1, int n1,
                const float* __restrict__ x2, __half* __restrict__ h2, int n2)
{
    int base = (blockIdx.x * 256 + threadIdx.x) * 16;
    const float* x; __half* hp;
    if (base < n0) { x = x0 + base; hp = h0 + base; }
    else if (base < n0 + n1) { base -= n0; x = x1 + base; hp = h1 + base; }
    else {
        base -= n0 + n1;
        if (base >= n2) return;
        x = x2 + base; hp = h2 + base;
    }
    float4 v0 = *(const float4*)(x);
    float4 v1 = *(const float4*)(x + 4);
    float4 v2 = *(const float4*)(x + 8);
    float4 v3 = *(const float4*)(x + 12);
    __half2 h[8];
    h[0] = __floats2half2_rn(v0.x, v0.y); h[1] = __floats2half2_rn(v0.z, v0.w);
    h[2] = __floats2half2_rn(v1.x, v1.y); h[3] = __floats2half2_rn(v1.z, v1.w);
    h[4] = __floats2half2_rn(v2.x, v2.y); h[5] = __floats2half2_rn(v2.z, v2.w);
    h[6] = __floats2half2_rn(v3.x, v3.y); h[7] = __floats2half2_rn(v3.z, v3.w);
    *(uint4*)(hp)     = *(uint4*)&h[0];
    *(uint4*)(hp + 8) = *(uint4*)&h[4];
}

// ---------------------------------------------------------------------
// Tensor-core GEMM: C = A[M,K] @ B[N,K]^T + bias[N]   (R12 exact)
// 64x128 CTA tile, 8 warps (2x4) of 32x32, 3-stage cp.async, 2 CTAs/SM.
// mode 0: C fp32; mode 1: Ch fp16
// ---------------------------------------------------------------------
#define STAGES 3
#define ATILE 5120            // 64 rows x 80B
#define SSTAGE 15360          // A 5120 + B 10240
#define GEMM_SMEM (STAGES * SSTAGE)   // 46080

__global__ __launch_bounds__(256, 2)
void gemm_mma(const __half* __restrict__ A, const __half* __restrict__ B,
              const float* __restrict__ bias, float* __restrict__ C,
              __half* __restrict__ Ch, int mode, int N, int K)
{
    extern __shared__ __align__(128) char smem[];
    const uint32_t sbase = smem_u32(smem);

    const int tid  = threadIdx.x;
    const int lane = tid & 31;
    const int wid  = tid >> 5;

    // banded CTA swizzle (L2-friendly): 8 bm rows per band
    const int id    = blockIdx.y * gridDim.x + blockIdx.x;
    const int bandw = 8 * gridDim.x;
    const int band  = id / bandw;
    const int rem   = id - band * bandw;
    const int bm = (band * 8 + (rem & 7)) * 64;
    const int bn = (rem >> 3) * 128;

    const int wm = (wid >> 2) * 32;
    const int wn = (wid & 3) * 32;

    const uint32_t aoff = (uint32_t)((wm + (lane & 15)) * 80 + (lane >> 4) * 16);
    const uint32_t boff = (uint32_t)(ATILE + (wn + (lane & 15)) * 80 + (lane >> 4) * 16);

    const __half* Abase = A + (size_t)bm * K;
    const __half* Bbase = B + (size_t)bn * K;

    float c[2][4][4];
    #pragma unroll
    for (int i = 0; i < 2; i++)
        #pragma unroll
        for (int j = 0; j < 4; j++)
            #pragma unroll
            for (int q = 0; q < 4; q++) c[i][j][q] = 0.0f;

    const int nk = K >> 5;

    auto issue = [&](int kt, int slot) {
        const int koff = kt * 32;
        const uint32_t st = sbase + slot * SSTAGE;
        {
            int row = tid >> 2, c16 = tid & 3;
            cp_async16(st + row * 80 + c16 * 16,
                       Abase + (size_t)row * K + koff + c16 * 8);
        }
        #pragma unroll
        for (int it = 0; it < 2; it++) {
            int idx = tid + it * 256;
            int row = idx >> 2, c16 = idx & 3;
            cp_async16(st + ATILE + row * 80 + c16 * 16,
                       Bbase + (size_t)row * K + koff + c16 * 8);
        }
    };

    issue(0, 0); cp_commit();
    issue(1, 1); cp_commit();

    for (int kt = 0; kt < nk; kt++) {
        cp_wait<1>();
        __syncthreads();

        const int nxt = kt + 2;
        if (nxt < nk) { issue(nxt, nxt % STAGES); }
        cp_commit();

        const uint32_t st = sbase + (kt % STAGES) * SSTAGE;
        #pragma unroll
        for (int kk = 0; kk < 2; kk++) {
            uint32_t ah[2][4], bh[2][4];
            #pragma unroll
            for (int i = 0; i < 2; i++)
                ldsm4(ah[i], st + aoff + i * 1280 + kk * 32);
            #pragma unroll
            for (int j2 = 0; j2 < 2; j2++)
                ldsm4(bh[j2], st + boff + j2 * 1280 + kk * 32);
            #pragma unroll
            for (int i = 0; i < 2; i++)
                #pragma unroll
                for (int j = 0; j < 4; j++) {
                    const int j2 = j >> 1, sl = j & 1;
                    mma16816(c[i][j], ah[i], bh[j2][sl], bh[j2][sl + 2]);
                }
        }
    }

    const int g = lane >> 2, t = lane & 3;
    #pragma unroll
    for (int j = 0; j < 4; j++) {
        const int col = bn + wn + j * 8 + t * 2;
        const float b0 = bias[col], b1 = bias[col + 1];
        #pragma unroll
        for (int i = 0; i < 2; i++) {
            const int row0 = bm + wm + i * 16 + g;
            float x0 = c[i][j][0] + b0, x1 = c[i][j][1] + b1;
            float x2 = c[i][j][2] + b0, x3 = c[i][j][3] + b1;
            if (mode == 0) {
                *(float2*)(C + (size_t)row0 * N + col)       = make_float2(x0, x1);
                *(float2*)(C + (size_t)(row0 + 8) * N + col) = make_float2(x2, x3);
            } else {
                *(__half2*)(Ch + (size_t)row0 * N + col)       = __floats2half2_rn(x0, x1);
                *(__half2*)(Ch + (size_t)(row0 + 8) * N + col) = __floats2half2_rn(x2, x3);
            }
        }
    }
}

// =====================================================================
// Tensorized flash attention (causal): Br=128, Bc=64, 8 warps  (R12 exact)
// 1-D grid, all-heaviest-first across heads. exp2-based softmax.
// =====================================================================
#define ASTR 272
#define QTILE (128 * ASTR)
#define KVTILE (64 * ASTR)
#define KVSTAGE (2 * KVTILE)
#define FLASH_SMEM (QTILE + 2 * KVSTAGE)   // 104448 -> 2 CTAs/SM

__global__ __launch_bounds__(256, 2)
void flash_attn_mma(const __half* __restrict__ qkvh, __half* __restrict__ ctxh)
{
    extern __shared__ __align__(128) char smem[];
    const uint32_t sb = smem_u32(smem);

    const int tid  = threadIdx.x;
    const int lane = tid & 31;
    const int wid  = tid >> 5;
    const int h  = blockIdx.x & (NH - 1);
    const int qb = (SQ / 128) - 1 - (blockIdx.x >> 4);
    const int q0w = qb * 128 + wid * 16;
    const int nkb = 2 * qb + 2;
    const float qs = 0.08838834764831845f * 1.4426950408889634f;  // scale*log2(e)

    {
        const size_t qrow = (size_t)(qb * 128) * QKVC + h * HD;
        const __half* qsrc = qkvh + qrow;
        #pragma unroll
        for (int it = 0; it < 8; it++) {
            int idx = tid + it * 256;
            int row = idx >> 4, ch = idx & 15;
            cp_async16(sb + row * ASTR + ch * 16,
                       qsrc + (size_t)row * QKVC + ch * 8);
        }
    }

    auto issueKV = [&](int kb, int slot) {
        const size_t roff = (size_t)(kb * 64) * QKVC + h * HD;
        const __half* base[2] = { qkvh + EM + roff, qkvh + 2 * EM + roff };
        const uint32_t st = sb + QTILE + slot * KVSTAGE;
        #pragma unroll
        for (int it = 0; it < 8; it++) {
            int idx = tid + it * 256;
            int arr = idx >> 10, rem = idx & 1023;
            int row = rem >> 4, ch = rem & 15;
            cp_async16(st + arr * KVTILE + row * ASTR + ch * 16,
                       base[arr] + (size_t)row * QKVC + ch * 8);
        }
    };

    issueKV(0, 0); cp_commit();
    issueKV(1, 1); cp_commit();

    float m[2] = { -1e30f, -1e30f };
    float l[2] = { 0.0f, 0.0f };
    float o[16][4];
    #pragma unroll
    for (int n = 0; n < 16; n++)
        #pragma unroll
        for (int q = 0; q < 4; q++) o[n][q] = 0.0f;

    const int g = lane >> 2, t = lane & 3;
    const uint32_t qaddr = sb + (wid * 16 + (lane & 15)) * ASTR + (lane >> 4) * 16;
    const uint32_t kvlane = (uint32_t)((lane & 15) * ASTR + (lane >> 4) * 16);

    for (int kb = 0; kb < nkb; kb++) {
        cp_wait<1>();
        __syncthreads();

        const int slot = kb & 1;
        const uint32_t kB = sb + QTILE + slot * KVSTAGE;
        const uint32_t vB = kB + KVTILE;
        const bool skip = (kb * 64 > q0w + 15);

        if (!skip) {
            float s[8][4];
            #pragma unroll
            for (int j = 0; j < 8; j++)
                #pragma unroll
                for (int q = 0; q < 4; q++) s[j][q] = 0.0f;

            #pragma unroll
            for (int ks = 0; ks < 8; ks++) {
                uint32_t ah4[4];
                ldsm4(ah4, qaddr + ks * 32);
                #pragma unroll
                for (int p2 = 0; p2 < 4; p2++) {
                    uint32_t bh4[4];
                    ldsm4(bh4, kB + kvlane + p2 * (16 * ASTR) + ks * 32);
                    #pragma unroll
                    for (int sl = 0; sl < 2; sl++)
                        mma16816(s[p2 * 2 + sl], ah4, bh4[sl], bh4[sl + 2]);
                }
            }

            const bool dm = (kb * 64 + 63 > q0w);
            const int r0 = q0w + g, r1 = q0w + 8 + g;
            float mx0 = -1e30f, mx1 = -1e30f;
            #pragma unroll
            for (int j = 0; j < 8; j++) {
                const int col = kb * 64 + 8 * j + 2 * t;
                float v0 = s[j][0] * qs, v1 = s[j][1] * qs;
                float v2 = s[j][2] * qs, v3 = s[j][3] * qs;
                if (dm) {
                    if (col     > r0) v0 = -1e30f;
                    if (col + 1 > r0) v1 = -1e30f;
                    if (col     > r1) v2 = -1e30f;
                    if (col + 1 > r1) v3 = -1e30f;
                }
                s[j][0] = v0; s[j][1] = v1; s[j][2] = v2; s[j][3] = v3;
                mx0 = fmaxf(mx0, fmaxf(v0, v1));
                mx1 = fmaxf(mx1, fmaxf(v2, v3));
            }
            mx0 = fmaxf(mx0, __shfl_xor_sync(0xffffffffu, mx0, 1));
            mx0 = fmaxf(mx0, __shfl_xor_sync(0xffffffffu, mx0, 2));
            mx1 = fmaxf(mx1, __shfl_xor_sync(0xffffffffu, mx1, 1));
            mx1 = fmaxf(mx1, __shfl_xor_sync(0xffffffffu, mx1, 2));

            const float mn0 = fmaxf(m[0], mx0);
            const float mn1 = fmaxf(m[1], mx1);
            float rs0 = 0.0f, rs1 = 0.0f;
            #pragma unroll
            for (int j = 0; j < 8; j++) {
                s[j][0] = exp2f(s[j][0] - mn0);
                s[j][1] = exp2f(s[j][1] - mn0);
                s[j][2] = exp2f(s[j][2] - mn1);
                s[j][3] = exp2f(s[j][3] - mn1);
                rs0 += s[j][0] + s[j][1];
                rs1 += s[j][2] + s[j][3];
            }
            rs0 += __shfl_xor_sync(0xffffffffu, rs0, 1);
            rs0 += __shfl_xor_sync(0xffffffffu, rs0, 2);
            rs1 += __shfl_xor_sync(0xffffffffu, rs1, 1);
            rs1 += __shfl_xor_sync(0xffffffffu, rs1, 2);

            const float f0 = exp2f(m[0] - mn0);
            const float f1 = exp2f(m[1] - mn1);
            l[0] = l[0] * f0 + rs0; l[1] = l[1] * f1 + rs1;
            m[0] = mn0; m[1] = mn1;
            #pragma unroll
            for (int n = 0; n < 16; n++) {
                o[n][0] *= f0; o[n][1] *= f0;
                o[n][2] *= f1; o[n][3] *= f1;
            }

            #pragma unroll
            for (int jp = 0; jp < 4; jp++) {
                uint32_t ph[4];
                {
                    const float* p0 = s[2 * jp];
                    const float* p1 = s[2 * jp + 1];
                    ph[0] = pack_h2(p0[0], p0[1]);
                    ph[1] = pack_h2(p0[2], p0[3]);
                    ph[2] = pack_h2(p1[0], p1[1]);
                    ph[3] = pack_h2(p1[2], p1[3]);
                }
                #pragma unroll
                for (int np = 0; np < 8; np++) {
                    uint32_t bh4[4];
                    ldsm4t(bh4, vB + kvlane + jp * (16 * ASTR) + np * 32);
                    mma16816(o[2 * np],     ph, bh4[0], bh4[1]);
                    mma16816(o[2 * np + 1], ph, bh4[2], bh4[3]);
                }
            }
        }

        __syncthreads();
        if (kb + 2 < nkb) issueKV(kb + 2, slot);
        cp_commit();
    }

    const float inv0 = 1.0f / l[0];
    const float inv1 = 1.0f / l[1];
    const int r0 = q0w + g, r1 = q0w + 8 + g;
    #pragma unroll
    for (int n = 0; n < 16; n++) {
        const int col = h * HD + n * 8 + 2 * t;
        *(__half2*)(ctxh + (size_t)r0 * EM + col) =
            __floats2half2_rn(o[n][0] * inv0, o[n][1] * inv0);
        *(__half2*)(ctxh + (size_t)r1 * EM + col) =
            __floats2half2_rn(o[n][2] * inv1, o[n][3] * inv1);
    }
}

// =====================================================================
extern "C" void kernel_launch(void* const* d_in, const int* in_sizes, int n_in,
                              void* d_out, int out_size)
{
    (void)in_sizes; (void)n_in; (void)out_size;
    const float* hs   = (const float*)d_in[0];
    const float* wqkv = (const float*)d_in[1];
    const float* bqkv = (const float*)d_in[2];
    const float* wo   = (const float*)d_in[3];
    const float* bo   = (const float*)d_in[4];
    float* out = (float*)d_out;

    __half *qkvh, *ah, *bh, *bh2;
    cudaGetSymbolAddress((void**)&qkvh, g_qkvh);
    cudaGetSymbolAddress((void**)&ah, g_ah);
    cudaGetSymbolAddress((void**)&bh, g_bh);
    cudaGetSymbolAddress((void**)&bh2, g_bh2);

    cudaFuncSetAttribute(gemm_mma, cudaFuncAttributeMaxDynamicSharedMemorySize, GEMM_SMEM);
    cudaFuncSetAttribute(flash_attn_mma, cudaFuncAttributeMaxDynamicSharedMemorySize, FLASH_SMEM);

    // 1) convert hs + Wqkv + Wo to fp16 in ONE launch
    const int n0 = SQ * EM, n1 = QKVC * EM, n2 = EM * EM;
    conv_f16_3<<<((n0 + n1 + n2) / 16 + 255) / 256, 256>>>(
        hs, ah, n0, wqkv, bh, n1, wo, bh2, n2);

    // 2) QKV projection -> fp16
    dim3 g1(QKVC / 128, SQ / 64);
    gemm_mma<<<g1, 256, GEMM_SMEM>>>(ah, bh, bqkv, nullptr, qkvh, 1, QKVC, EM);

    // 3) causal flash attention -> ctx fp16 (overwrites ah)
    flash_attn_mma<<<(SQ / 128) * NH, 256, FLASH_SMEM>>>(qkvh, ah);

    // 4) output projection -> fp32 out (weights from bh2)
    dim3 g3(EM / 128, SQ / 64);
    gemm_mma<<<g3, 256, GEMM_SMEM>>>(ah, bh2, bo, out, nullptr, 0, EM, EM);
}